// round 2
// baseline (speedup 1.0000x reference)
#include <cuda_runtime.h>
#include <cuda_bf16.h>

#define M 512
#define SL 16            // nodes (slots) per lane: 32 lanes * 16 = 512
#define FULL 0xffffffffu
#define EPS_F 1e-12f
#define DEAD 0xffffffffu // sentinel bits for visited nodes (max uint)

// Deterministic scratch for per-primitive means + completion counter.
__device__ float    g_mean_scratch[4096];
__device__ unsigned g_done_count = 0;

__global__ void __launch_bounds__(32) prim_mst_warp(
    const float* __restrict__ xyz,
    const float* __restrict__ alpha_p,
    float* __restrict__ out,
    int P, int n, int B, int nprim)
{
    __shared__ float sx[M], sy[M], sz[M];
    __shared__ float s_cost[M];
    __shared__ int   s_par[M];

    const int lane = threadIdx.x;
    const int bp   = blockIdx.x;                   // primitive id in [0, B*P)
    const float* src = xyz + (size_t)bp * (3 * M); // primitives contiguous

    // Load + deinterleave xyz into SoA shared (coalesced reads, one time).
    for (int i = lane; i < 3 * M; i += 32) {
        float v = __ldg(src + i);
        int row = i / 3, c = i - 3 * row;
        if (c == 0)      sx[row] = v;
        else if (c == 1) sy[row] = v;
        else             sz[row] = v;
    }
    __syncwarp();

    // Own node coordinates in registers (blocked assignment: lane owns [lane*16, lane*16+16)).
    const int base_nid = lane * SL;
    float pxs[SL], pys[SL], pzs[SL];
    #pragma unroll
    for (int j = 0; j < SL; ++j) {
        pxs[j] = sx[base_nid + j];
        pys[j] = sy[base_nid + j];
        pzs[j] = sz[base_nid + j];
    }

    // Init: best_d = distance to node 0 (exact reference arithmetic: no FMA
    // contraction, fmaxf(s,EPS), IEEE sqrt). Values kept as uint bits:
    // for non-negative floats, uint order == float order. DEAD marks visited.
    const float x0 = sx[0], y0 = sy[0], z0 = sz[0];
    unsigned mv[SL];          // best_d bits, or DEAD if visited
    #pragma unroll
    for (int j = 0; j < SL; ++j) {
        float dx = __fsub_rn(pxs[j], x0);
        float dy = __fsub_rn(pys[j], y0);
        float dz = __fsub_rn(pzs[j], z0);
        float s  = __fadd_rn(__fadd_rn(__fmul_rn(dx, dx), __fmul_rn(dy, dy)), __fmul_rn(dz, dz));
        s = fmaxf(s, EPS_F);
        mv[j] = __float_as_uint(__fsqrt_rn(s));
        s_par[base_nid + j] = 0;    // best_p init = 0 (matches reference)
    }
    if (lane == 0) mv[0] = DEAD;    // node 0 visited from the start
    __syncwarp();

    // ---- Prim's algorithm: 511 sequential selections, warp-synchronous, no barriers ----
    for (int it = 0; it < M - 1; ++it) {
        // Local first-occurrence argmin over 16 slots (strict < prefers lower index).
        unsigned tv[SL]; int ti[SL];
        #pragma unroll
        for (int j = 0; j < SL; ++j) { tv[j] = mv[j]; ti[j] = j; }
        #pragma unroll
        for (int step = 1; step < SL; step <<= 1) {
            #pragma unroll
            for (int j = 0; j < SL; j += 2 * step) {
                bool t = tv[j + step] < tv[j];
                tv[j] = t ? tv[j + step] : tv[j];
                ti[j] = t ? ti[j + step] : ti[j];
            }
        }
        const unsigned lval = tv[0];
        const int      lidx = base_nid + ti[0];

        // Warp argmin: value min, then lowest lane among value-ties (first occurrence).
        unsigned g    = __reduce_min_sync(FULL, lval);
        unsigned ball = __ballot_sync(FULL, lval == g);
        int      w    = __ffs(ball) - 1;
        int      u    = __shfl_sync(FULL, lidx, w);

        // Record the selected edge cost (parent already sits in s_par[u]).
        if (lane == 0) s_cost[u] = __uint_as_float(g);

        // Relax all nodes against u with exact reference arithmetic.
        const float ux = sx[u], uy = sy[u], uz = sz[u];
        const int   ul = u - base_nid;   // u's slot if owned by this lane, else out of [0,16)
        #pragma unroll
        for (int j = 0; j < SL; ++j) {
            float dx = __fsub_rn(pxs[j], ux);
            float dy = __fsub_rn(pys[j], uy);
            float dz = __fsub_rn(pzs[j], uz);
            float s  = __fadd_rn(__fadd_rn(__fmul_rn(dx, dx), __fmul_rn(dy, dy)), __fmul_rn(dz, dz));
            s = fmaxf(s, EPS_F);
            unsigned db = __float_as_uint(__fsqrt_rn(s));
            bool isu   = (ul == j);
            bool alive = (mv[j] != DEAD);
            bool upd   = alive && !isu && (db < mv[j]);   // uint cmp == float cmp (positives)
            if (upd) { mv[j] = db; s_par[base_nid + j] = u; }
            if (isu) { mv[j] = DEAD; }                    // u becomes visited
        }
    }
    __syncwarp();

    // Node 0: root of the tree.
    if (lane == 0) { s_cost[0] = 0.0f; s_par[0] = -1; }
    __syncwarp();

    // Mean MST edge length (sum of 512 costs / 511).
    float sum = 0.0f;
    #pragma unroll
    for (int j = 0; j < SL; ++j) sum += s_cost[base_nid + j];
    #pragma unroll
    for (int off = 16; off; off >>= 1) sum += __shfl_xor_sync(FULL, sum, off);
    const float mean  = sum / (float)(M - 1);
    const float alpha = *alpha_p;
    const float thr   = alpha * mean;

    // Outputs: dist and assign (primitive-local parent -> per-cloud global index).
    const int b     = bp / P;
    const int pl    = bp - b * P;
    const int gbase = pl * M;
    const size_t go = (size_t)b * n + gbase;
    #pragma unroll
    for (int j = 0; j < SL; ++j) {
        const int nid = base_nid + j;
        const float c = s_cost[nid];
        const bool mk = c > thr;
        out[go + nid]                   = mk ? c : 0.0f;
        out[(size_t)B * n + go + nid]   = mk ? (float)(s_par[nid] + gbase) : -1.0f;
    }

    // Fused per-cloud mean-of-means: last-block-done pattern (deterministic).
    if (lane == 0) g_mean_scratch[bp] = mean;
    __threadfence();
    __syncwarp();
    unsigned old = 0;
    if (lane == 0) old = atomicAdd(&g_done_count, 1u);
    old = __shfl_sync(FULL, old, 0);
    if (old == (unsigned)(nprim - 1)) {
        __threadfence();
        for (int b2 = lane; b2 < B; b2 += 32) {
            float s = 0.0f;
            for (int p = 0; p < P; ++p) s += g_mean_scratch[b2 * P + p];
            out[(size_t)2 * B * n + b2] = s / (float)P;
        }
        if (lane == 0) g_done_count = 0;   // reset for next graph replay
    }
}

extern "C" void kernel_launch(void* const* d_in, const int* in_sizes, int n_in,
                              void* d_out, int out_size)
{
    const float* xyz   = (const float*)d_in[0];
    // d_in[1] = primitive_size (512, baked in as M)
    const float* alpha = (const float*)d_in[2];

    const int Bn = in_sizes[0] / 3;     // B*n
    const int B  = out_size - 2 * Bn;   // out = 2*B*n + B floats
    const int n  = Bn / B;
    const int P  = n / M;
    const int nprim = B * P;

    prim_mst_warp<<<nprim, 32>>>(xyz, alpha, (float*)d_out, P, n, B, nprim);
}

// round 3
// speedup vs baseline: 2.7919x; 2.7919x over previous
#include <cuda_runtime.h>
#include <cuda_bf16.h>

#define M 512
#define T 128                 // threads per primitive
#define SL 4                  // nodes per thread (T*SL == M)
#define NWP (T / 32)          // 4 warps
#define FULL 0xffffffffu
#define EPS_F 1e-12f
#define DEAD 0xffffffffu      // sentinel bits for visited nodes (max uint)

__device__ float    g_mean_scratch[4096];
__device__ unsigned g_done_count = 0;

__global__ void __launch_bounds__(T) prim_mst(
    const float* __restrict__ xyz,
    const float* __restrict__ alpha_p,
    float* __restrict__ out,
    int P, int n, int B, int nprim)
{
    __shared__ float sx[M], sy[M], sz[M];
    __shared__ unsigned long long s_pack[2][NWP];  // double-buffered per-warp winners
    __shared__ float s_red[NWP];
    __shared__ unsigned s_old;

    const int tid  = threadIdx.x;
    const int lane = tid & 31;
    const int warp = tid >> 5;
    const int bp   = blockIdx.x;                    // primitive id
    const float* src = xyz + (size_t)bp * (3 * M);

    // One-time coalesced load + deinterleave into SoA shared.
    for (int i = tid; i < 3 * M; i += T) {
        float v = __ldg(src + i);
        int row = i / 3, c = i - 3 * row;
        if (c == 0)      sx[row] = v;
        else if (c == 1) sy[row] = v;
        else             sz[row] = v;
    }
    __syncthreads();

    // Blocked ownership: thread owns nodes [tid*4, tid*4+4) -> lane order == node order.
    const int base = tid * SL;
    float px[SL], py[SL], pz[SL], cost[SL];
    int   bpar[SL];
    unsigned mv[SL];   // best connection cost bits (uint order == float order for positives)

    const float x0 = sx[0], y0 = sy[0], z0 = sz[0];
    #pragma unroll
    for (int j = 0; j < SL; ++j) {
        px[j] = sx[base + j]; py[j] = sy[base + j]; pz[j] = sz[base + j];
        // Exact reference arithmetic: no FMA contraction, fmaxf(s,EPS), IEEE sqrt.
        float dx = __fsub_rn(px[j], x0);
        float dy = __fsub_rn(py[j], y0);
        float dz = __fsub_rn(pz[j], z0);
        float s  = __fadd_rn(__fadd_rn(__fmul_rn(dx, dx), __fmul_rn(dy, dy)), __fmul_rn(dz, dz));
        s = fmaxf(s, EPS_F);
        mv[j]   = __float_as_uint(__fsqrt_rn(s));
        cost[j] = 0.0f;
        bpar[j] = 0;                 // best_p init = 0 (matches reference)
    }
    if (tid == 0) { mv[0] = DEAD; bpar[0] = -1; }   // node 0 = root, visited

    // ---- Prim: 511 sequential selections, ONE barrier per iteration ----
    for (int it = 0; it < M - 1; ++it) {
        // Local first-occurrence argmin over 4 slots (strict < prefers lower index).
        unsigned va = mv[0], vb = mv[1], vc = mv[2], vd = mv[3];
        unsigned v01 = va; int i01 = 0;
        if (vb < v01) { v01 = vb; i01 = 1; }
        unsigned v23 = vc; int i23 = 2;
        if (vd < v23) { v23 = vd; i23 = 3; }
        unsigned lval = v01; int lidx = i01;
        if (v23 < lval) { lval = v23; lidx = i23; }
        lidx += base;   // global node index

        // Warp argmin: REDUX value min, lowest lane among ties = first occurrence.
        unsigned g    = __reduce_min_sync(FULL, lval);
        unsigned ball = __ballot_sync(FULL, lval == g);
        int      w    = __ffs(ball) - 1;
        int      li   = __shfl_sync(FULL, lidx, w);

        // Publish per-warp winner packed (value high, index low) -> min == (min val, min idx).
        if (lane == 0)
            s_pack[it & 1][warp] = ((unsigned long long)g << 32) | (unsigned)li;
        __syncthreads();

        // Every thread redundantly reduces the 4 warp winners (no 2nd barrier).
        unsigned long long pk = s_pack[it & 1][0];
        #pragma unroll
        for (int q = 1; q < NWP; ++q) {
            unsigned long long t = s_pack[it & 1][q];
            if (t < pk) pk = t;
        }
        const int      u    = (int)(unsigned)pk;
        const unsigned uval = (unsigned)(pk >> 32);

        // Relax all 4 owned slots against u (exact reference arithmetic).
        const float ux = sx[u], uy = sy[u], uz = sz[u];
        #pragma unroll
        for (int j = 0; j < SL; ++j) {
            float dx = __fsub_rn(px[j], ux);
            float dy = __fsub_rn(py[j], uy);
            float dz = __fsub_rn(pz[j], uz);
            float s  = __fadd_rn(__fadd_rn(__fmul_rn(dx, dx), __fmul_rn(dy, dy)), __fmul_rn(dz, dz));
            s = fmaxf(s, EPS_F);
            unsigned db = __float_as_uint(__fsqrt_rn(s));
            bool isu   = (u == base + j);
            bool alive = (mv[j] != DEAD);
            bool upd   = alive && !isu && (db < mv[j]);
            if (upd) { mv[j] = db; bpar[j] = u; }
            if (isu) { mv[j] = DEAD; cost[j] = __uint_as_float(uval); }  // selection freezes cost/parent
        }
    }

    // ---- Mean MST edge length over the primitive ----
    float sum = ((cost[0] + cost[1]) + (cost[2] + cost[3]));
    #pragma unroll
    for (int off = 16; off; off >>= 1) sum += __shfl_xor_sync(FULL, sum, off);
    if (lane == 0) s_red[warp] = sum;
    __syncthreads();
    float tot = s_red[0];
    #pragma unroll
    for (int q = 1; q < NWP; ++q) tot += s_red[q];
    const float mean  = tot / (float)(M - 1);
    const float alpha = *alpha_p;
    const float thr   = alpha * mean;

    // ---- Outputs (vectorized float4: base is 4-aligned) ----
    const int b     = bp / P;
    const int pl    = bp - b * P;
    const int gbase = pl * M;
    const size_t go = (size_t)b * n + gbase + base;

    float4 dv, av;
    float* dp = &dv.x; float* ap = &av.x;
    #pragma unroll
    for (int j = 0; j < SL; ++j) {
        const float c = cost[j];
        const bool mk = c > thr;
        dp[j] = mk ? c : 0.0f;
        ap[j] = mk ? (float)(bpar[j] + gbase) : -1.0f;
    }
    *(float4*)(out + go)                 = dv;
    *(float4*)(out + (size_t)B * n + go) = av;

    // ---- Fused per-cloud mean-of-means: last-block-done pattern ----
    if (tid == 0) g_mean_scratch[bp] = mean;
    __threadfence();
    if (tid == 0) s_old = atomicAdd(&g_done_count, 1u);
    __syncthreads();
    if (s_old == (unsigned)(nprim - 1)) {
        __threadfence();
        for (int b2 = tid; b2 < B; b2 += T) {
            float s = 0.0f;
            for (int p = 0; p < P; ++p) s += g_mean_scratch[b2 * P + p];
            out[(size_t)2 * B * n + b2] = s / (float)P;
        }
        if (tid == 0) g_done_count = 0;   // reset for next graph replay
    }
}

extern "C" void kernel_launch(void* const* d_in, const int* in_sizes, int n_in,
                              void* d_out, int out_size)
{
    const float* xyz   = (const float*)d_in[0];
    // d_in[1] = primitive_size (512, compile-time M)
    const float* alpha = (const float*)d_in[2];

    const int Bn = in_sizes[0] / 3;     // B*n
    const int B  = out_size - 2 * Bn;   // out = 2*B*n + B floats
    const int n  = Bn / B;
    const int P  = n / M;
    const int nprim = B * P;

    prim_mst<<<nprim, T>>>(xyz, alpha, (float*)d_out, P, n, B, nprim);
}